// round 9
// baseline (speedup 1.0000x reference)
#include <cuda_runtime.h>
#include <cstdint>
#include <cstddef>

// CTC loss (faithful to reference incl. input_len = C bug).
// B=512, T=512 (row stride), C=128, Tu=128, L=64, S=129, blank=127.
// One warp per batch row (512 warps), but packed as 8-warp / 256-thread
// blocks (64 blocks -> 1 block/SM -> 2 warps per SMSP) so the scheduler
// interleaves two independent rows and hides each warp's SHFL/LDS latency.
// Lane holds states 4*lane+j (j=0..3), lane31 also state 128.
// Linear domain, power-of-2 rescale per 8 steps, 128 uniform steps from
// virtual init a0=1@lane0. cp.async staging, per-warp 4-buffer ring.

#define B_    512
#define T_    512
#define C_    128
#define L_    64
#define BLANK 127
#define EPSF  (1e-7f)
#define LN2F  0.69314718055994530942f

#define WARPS  8            // warps (rows) per block
#define CHUNK  8
#define NBUF   4
#define NCHUNK 16           // 128 timesteps / CHUNK
#define DEPTH  3
#define SMEM_BYTES (WARPS * NBUF * CHUNK * C_ * 4)   // 128 KB

__device__ __forceinline__ void cpasync16(uint32_t saddr, const void* g) {
    asm volatile("cp.async.cg.shared.global [%0], [%1], 16;" :: "r"(saddr), "l"(g));
}
__device__ __forceinline__ void cp_commit() { asm volatile("cp.async.commit_group;"); }
__device__ __forceinline__ void cp_wait2()  { asm volatile("cp.async.wait_group 2;"); }

__global__ __launch_bounds__(WARPS * 32, 1)
void ctc_kernel(const int* __restrict__ y_true,
                const float* __restrict__ y_pred,
                float* __restrict__ out)
{
    extern __shared__ float sm[];     // [WARPS][NBUF][CHUNK][C_]
    const unsigned FULL = 0xffffffffu;
    const int lane = threadIdx.x & 31;
    const int w    = threadIdx.x >> 5;
    const int b    = blockIdx.x * WARPS + w;

    float* mybuf = sm + (size_t)w * NBUF * CHUNK * C_;
    const uint32_t smbase = (uint32_t)__cvta_generic_to_shared(mybuf);

    const float* __restrict__ row = y_pred + (size_t)b * T_ * C_;

    // labels (coalesced int2): lane -> labels 2*lane, 2*lane+1
    const int2 lpair = ((const int2*)(y_true + b * L_))[lane];
    const int l0 = lpair.x, l1 = lpair.y;
    const int lp = __shfl_up_sync(FULL, l1, 1);
    const float sk1 = (lane > 0 && l0 != lp) ? 1.f : 0.f;   // state 4l+1 skip
    const float sk3 = (l1 != l0) ? 1.f : 0.f;               // state 4l+3 skip

    auto issue_chunk = [&](int c) {
        const float* g = row + (size_t)c * CHUNK * C_ + lane * 4;
        const uint32_t s = smbase +
            (uint32_t)(((c & (NBUF - 1)) * CHUNK * C_ + lane * 4) * 4);
        #pragma unroll
        for (int j = 0; j < CHUNK; ++j)
            cpasync16(s + j * C_ * 4, g + j * C_);
    };

    // ---- alpha state: virtual init => 128 uniform steps ---------------------
    float a0 = (lane == 0) ? 1.f : 0.f;
    float a1 = 0.f, a2 = 0.f, a3 = 0.f, a4 = 0.f;
    float n3 = 0.f;
    int etot = 0;

    // ---- pipeline prologue ---------------------------------------------------
    #pragma unroll
    for (int k = 0; k < DEPTH; ++k) { issue_chunk(k); cp_commit(); }

    for (int c = 0; c < NCHUNK; ++c) {
        if (c + DEPTH < NCHUNK) issue_chunk(c + DEPTH);
        cp_commit();
        cp_wait2(); __syncwarp();

        const float* srow = mybuf + (size_t)(c & (NBUF - 1)) * CHUNK * C_;

        #pragma unroll
        for (int j = 0; j < CHUNK; ++j) {
            const float q0 = srow[j * C_ + l0]    + EPSF;
            const float q1 = srow[j * C_ + l1]    + EPSF;
            const float qB = srow[j * C_ + BLANK] + EPSF;

            const float na0 = (a0 + n3) * qB;                   // s=4l (blank)
            const float na1 = fmaf(a1 + a0, q0, (sk1 * q0) * n3);
            const float na2 = (a2 + a1) * qB;                   // blank
            const float na3 = fmaf(a3 + a2, q1, (sk3 * q1) * a1);
            const float na4 = (a4 + a3) * qB;                   // s=128
            a0 = na0; a1 = na1; a2 = na2; a3 = na3; a4 = na4;
            const float t = __shfl_up_sync(FULL, a3, 1);        // early issue
            n3 = (lane == 0) ? 0.f : t;
        }

        // power-of-two rescale (alpha >= 0 -> float bits monotonic as s32)
        float mv = fmaxf(fmaxf(a0, a1), fmaxf(fmaxf(a2, a3), a4));
        int rb;
        asm volatile("redux.sync.max.s32 %0, %1, 0xffffffff;"
                     : "=r"(rb) : "r"(__float_as_int(mv)));
        const int e = (rb >> 23) - 127;
        const float sc = __int_as_float((127 - e) << 23);       // 2^-e
        a0 *= sc; a1 *= sc; a2 *= sc; a3 *= sc; a4 *= sc; n3 *= sc;
        etot += e;
    }

    // ---- loss = -( ln(alpha[127] + alpha[128]) + etot*ln2 ) ------------------
    if (lane == 31) {
        const float s = a3 + a4;        // states 127, 128
        out[b] = -(__logf(s) + (float)etot * LN2F);
    }
}

extern "C" void kernel_launch(void* const* d_in, const int* in_sizes, int n_in,
                              void* d_out, int out_size)
{
    const int* y_true;
    const float* y_pred;
    if (n_in >= 2 && in_sizes[0] == B_ * L_) {
        y_true = (const int*)d_in[0];
        y_pred = (const float*)d_in[1];
    } else {
        y_true = (const int*)d_in[1];
        y_pred = (const float*)d_in[0];
    }
    float* out = (float*)d_out;

    // 128 KB dynamic smem (static limit is 48 KB). Attribute set is a host-side
    // function-attribute update: no allocation, no stream op, capture-safe.
    cudaFuncSetAttribute(ctc_kernel,
                         cudaFuncAttributeMaxDynamicSharedMemorySize, SMEM_BYTES);

    ctc_kernel<<<B_ / WARPS, WARPS * 32, SMEM_BYTES>>>(y_true, y_pred, out);
}